// round 1
// baseline (speedup 1.0000x reference)
#include <cuda_runtime.h>

#define HH 64
#define WW 64
#define CC 64
#define HWPIX 4096
#define NT 216
#define EMBROW 36928   // 64*577
#define FSTRIDE 580    // padded F row (577 -> 580, mult of 4)
#define NP 32          // pixel chunk
#define PSTRIDE 34     // padded patch row
#define W2STRIDE 68    // padded w2 row

// ---------- device scratch (no allocation allowed) ----------
__device__ __align__(16) float g_h[HWPIX * CC];   // h in HWC layout
__device__ int g_count[NT];
__device__ int g_start[NT];
__device__ int g_cursor[NT];
__device__ int g_pix[HWPIX];

// ---------- zero counters ----------
__global__ void k_zero() {
    int i = blockIdx.x * blockDim.x + threadIdx.x;
    if (i < NT) g_count[i] = 0;
}

// ---------- body1: grouped 3x3 conv + bias + relu -> g_h (HWC) ----------
__global__ __launch_bounds__(256) void k_conv1(const float* __restrict__ x,
                                               const float* __restrict__ w1,
                                               const float* __restrict__ b1) {
    __shared__ float xs[16][18][18];
    __shared__ __align__(16) float wsm[144 * 20];
    int g = blockIdx.z;
    int y0 = blockIdx.y * 16, x0 = blockIdx.x * 16;
    int tid = threadIdx.y * 16 + threadIdx.x;

    // weights for this group, transposed: wsm[(ci*9+s)*20 + oc]
    for (int idx = tid; idx < 2304; idx += 256) {
        int oc = idx / 144, m = idx - oc * 144;
        wsm[m * 20 + oc] = w1[(g * 16 + oc) * 144 + m];
    }
    // x tile with halo (16 ch x 18 x 18), zero padded
    for (int idx = tid; idx < 16 * 324; idx += 256) {
        int ci = idx / 324, r = idx - ci * 324;
        int yl = r / 18, xl = r - yl * 18;
        int yy = y0 - 1 + yl, xx = x0 - 1 + xl;
        float v = 0.f;
        if ((unsigned)yy < 64u && (unsigned)xx < 64u)
            v = x[(g * 16 + ci) * HWPIX + yy * 64 + xx];
        xs[ci][yl][xl] = v;
    }
    __syncthreads();

    int ty = threadIdx.y, tx = threadIdx.x;
    float acc[16];
#pragma unroll
    for (int oc = 0; oc < 16; oc++) acc[oc] = __ldg(&b1[g * 16 + oc]);

    for (int ci = 0; ci < 16; ci++) {
#pragma unroll
        for (int s = 0; s < 9; s++) {
            float xv = xs[ci][ty + s / 3][tx + s % 3];
            int m = ci * 9 + s;
#pragma unroll
            for (int q = 0; q < 4; q++) {
                float4 w = *(const float4*)&wsm[m * 20 + q * 4];
                acc[q * 4 + 0] += w.x * xv;
                acc[q * 4 + 1] += w.y * xv;
                acc[q * 4 + 2] += w.z * xv;
                acc[q * 4 + 3] += w.w * xv;
            }
        }
    }
    int gy = y0 + ty, gx = x0 + tx;
    float* hp = &g_h[(gy * 64 + gx) * 64 + g * 16];
#pragma unroll
    for (int q = 0; q < 4; q++) {
        float4 r;
        r.x = fmaxf(acc[q * 4 + 0], 0.f);
        r.y = fmaxf(acc[q * 4 + 1], 0.f);
        r.z = fmaxf(acc[q * 4 + 2], 0.f);
        r.w = fmaxf(acc[q * 4 + 3], 0.f);
        *(float4*)&hp[q * 4] = r;
    }
}

// ---------- histogram ----------
__global__ void k_hist(const int* __restrict__ buckets) {
    int i = blockIdx.x * 256 + threadIdx.x;
    atomicAdd(&g_count[buckets[i]], 1);
}

// ---------- exclusive scan (216 counters, one block) ----------
__global__ void k_scan() {
    __shared__ int s[256];
    int tid = threadIdx.x;
    int v = (tid < NT) ? g_count[tid] : 0;
    s[tid] = v;
    __syncthreads();
    for (int off = 1; off < 256; off <<= 1) {
        int t = (tid >= off) ? s[tid - off] : 0;
        __syncthreads();
        s[tid] += t;
        __syncthreads();
    }
    if (tid < NT) {
        int excl = s[tid] - v;
        g_start[tid] = excl;
        g_cursor[tid] = excl;
    }
}

// ---------- scatter pixel indices grouped by bucket ----------
__global__ void k_scatter(const int* __restrict__ buckets) {
    int i = blockIdx.x * 256 + threadIdx.x;
    int b = buckets[i];
    int pos = atomicAdd(&g_cursor[b], 1);
    g_pix[pos] = i;
}

// ---------- main: per-bucket dynamic conv GEMM + fused 1x1 + residual ----------
__global__ __launch_bounds__(256) void k_main(const float* __restrict__ x,
                                              const float* __restrict__ emb,
                                              const float* __restrict__ w2,
                                              const float* __restrict__ b2,
                                              float* __restrict__ out) {
    extern __shared__ float sm[];
    float* Fs = sm;                            // 64 * 580
    float* w2s = sm + 64 * FSTRIDE;            // 64 * 68
    float* patch = w2s + 64 * W2STRIDE;        // 144 * 34 (aliased as zbuf)
    __shared__ int pixels[NP];

    int t = blockIdx.x;
    int tid = threadIdx.x;
    int n = g_count[t];
    int start = g_start[t];

    // load this bucket's filter (64 x 577) into smem, row-padded
    const float* e = emb + (size_t)t * EMBROW;
    for (int idx = tid; idx < EMBROW; idx += 256) {
        int o = idx / 577;
        int j = idx - o * 577;
        Fs[o * FSTRIDE + j] = e[idx];
    }
    // w2 into smem, row-padded
    for (int idx = tid; idx < 4096; idx += 256) {
        w2s[(idx >> 6) * W2STRIDE + (idx & 63)] = w2[idx];
    }
    __syncthreads();

    int othr = tid >> 4;  // 0..15  -> o = othr*4 + i
    int pthr = tid & 15;  // 0..15  -> p = pthr*2 + j

    for (int pb = 0; pb < n; pb += NP) {
        int npc = min(NP, n - pb);
        __syncthreads();  // protect pixels[] / zbuf from previous iteration
        if (tid < NP) {
            int k = min(tid, npc - 1);  // clamp: padded lanes duplicate a real pixel
            pixels[tid] = g_pix[start + pb + k];
        }
        __syncthreads();

        float acc[4][2] = {{0.f, 0.f}, {0.f, 0.f}, {0.f, 0.f}, {0.f, 0.f}};

        for (int c0 = 0; c0 < 64; c0 += 16) {
            __syncthreads();
            // load patch chunk: channels [c0, c0+16), all 9 taps, all 32 pixels
            for (int q = tid; q < 1152; q += 256) {
                int p = q / 36;
                int r = q - p * 36;
                int cq = r & 3;
                int s = r >> 2;
                int pix = pixels[p];
                int py = pix >> 6, px = pix & 63;
                int yy = py + s / 3 - 1, xx = px + s % 3 - 1;
                float4 v = make_float4(0.f, 0.f, 0.f, 0.f);
                if ((unsigned)yy < 64u && (unsigned)xx < 64u)
                    v = *(const float4*)&g_h[((yy << 6) + xx) * 64 + c0 + cq * 4];
                int clb = cq * 4;
                patch[((clb + 0) * 9 + s) * PSTRIDE + p] = v.x;
                patch[((clb + 1) * 9 + s) * PSTRIDE + p] = v.y;
                patch[((clb + 2) * 9 + s) * PSTRIDE + p] = v.z;
                patch[((clb + 3) * 9 + s) * PSTRIDE + p] = v.w;
            }
            __syncthreads();

            const float* Fb = Fs + (othr * 4) * FSTRIDE + c0 * 9;
            const float* Pb = patch + pthr * 2;
#pragma unroll 2
            for (int ck = 0; ck < 144; ck += 4) {
                float4 f0 = *(const float4*)&Fb[0 * FSTRIDE + ck];
                float4 f1 = *(const float4*)&Fb[1 * FSTRIDE + ck];
                float4 f2 = *(const float4*)&Fb[2 * FSTRIDE + ck];
                float4 f3 = *(const float4*)&Fb[3 * FSTRIDE + ck];
                float2 q0 = *(const float2*)&Pb[(ck + 0) * PSTRIDE];
                float2 q1 = *(const float2*)&Pb[(ck + 1) * PSTRIDE];
                float2 q2 = *(const float2*)&Pb[(ck + 2) * PSTRIDE];
                float2 q3 = *(const float2*)&Pb[(ck + 3) * PSTRIDE];
                acc[0][0] += f0.x * q0.x; acc[0][0] += f0.y * q1.x; acc[0][0] += f0.z * q2.x; acc[0][0] += f0.w * q3.x;
                acc[0][1] += f0.x * q0.y; acc[0][1] += f0.y * q1.y; acc[0][1] += f0.z * q2.y; acc[0][1] += f0.w * q3.y;
                acc[1][0] += f1.x * q0.x; acc[1][0] += f1.y * q1.x; acc[1][0] += f1.z * q2.x; acc[1][0] += f1.w * q3.x;
                acc[1][1] += f1.x * q0.y; acc[1][1] += f1.y * q1.y; acc[1][1] += f1.z * q2.y; acc[1][1] += f1.w * q3.y;
                acc[2][0] += f2.x * q0.x; acc[2][0] += f2.y * q1.x; acc[2][0] += f2.z * q2.x; acc[2][0] += f2.w * q3.x;
                acc[2][1] += f2.x * q0.y; acc[2][1] += f2.y * q1.y; acc[2][1] += f2.z * q2.y; acc[2][1] += f2.w * q3.y;
                acc[3][0] += f3.x * q0.x; acc[3][0] += f3.y * q1.x; acc[3][0] += f3.z * q2.x; acc[3][0] += f3.w * q3.x;
                acc[3][1] += f3.x * q0.y; acc[3][1] += f3.y * q1.y; acc[3][1] += f3.z * q2.y; acc[3][1] += f3.w * q3.y;
            }
        }

        // epilogue: dyn bias + relu -> zbuf (aliases patch)
        __syncthreads();
        float* zbuf = patch;
#pragma unroll
        for (int i = 0; i < 4; i++) {
            int o = othr * 4 + i;
            float bsum = Fs[o * FSTRIDE + 576];
            zbuf[o * PSTRIDE + pthr * 2 + 0] = fmaxf(acc[i][0] + bsum, 0.f);
            zbuf[o * PSTRIDE + pthr * 2 + 1] = fmaxf(acc[i][1] + bsum, 0.f);
        }
        __syncthreads();

        // 1x1 conv + b2
        float a2[4][2];
#pragma unroll
        for (int i = 0; i < 4; i++) {
            float bv = __ldg(&b2[othr * 4 + i]);
            a2[i][0] = bv;
            a2[i][1] = bv;
        }
#pragma unroll 4
        for (int o4 = 0; o4 < 64; o4 += 4) {
            float2 z0 = *(const float2*)&zbuf[(o4 + 0) * PSTRIDE + pthr * 2];
            float2 z1 = *(const float2*)&zbuf[(o4 + 1) * PSTRIDE + pthr * 2];
            float2 z2 = *(const float2*)&zbuf[(o4 + 2) * PSTRIDE + pthr * 2];
            float2 z3 = *(const float2*)&zbuf[(o4 + 3) * PSTRIDE + pthr * 2];
#pragma unroll
            for (int i = 0; i < 4; i++) {
                float4 w = *(const float4*)&w2s[(othr * 4 + i) * W2STRIDE + o4];
                a2[i][0] += w.x * z0.x; a2[i][0] += w.y * z1.x; a2[i][0] += w.z * z2.x; a2[i][0] += w.w * z3.x;
                a2[i][1] += w.x * z0.y; a2[i][1] += w.y * z1.y; a2[i][1] += w.z * z2.y; a2[i][1] += w.w * z3.y;
            }
        }

        // residual + relu + store (masked for padded lanes)
#pragma unroll
        for (int j = 0; j < 2; j++) {
            int p = pthr * 2 + j;
            if (p < npc) {
                int pix = pixels[p];
#pragma unroll
                for (int i = 0; i < 4; i++) {
                    int oo = othr * 4 + i;
                    float v = a2[i][j] + __ldg(&x[oo * HWPIX + pix]);
                    out[oo * HWPIX + pix] = fmaxf(v, 0.f);
                }
            }
        }
    }
}

extern "C" void kernel_launch(void* const* d_in, const int* in_sizes, int n_in,
                              void* d_out, int out_size) {
    const float* x   = (const float*)d_in[0];
    const int* bk    = (const int*)d_in[1];
    const float* w1  = (const float*)d_in[2];
    const float* b1  = (const float*)d_in[3];
    const float* emb = (const float*)d_in[4];
    const float* w2  = (const float*)d_in[5];
    const float* b2  = (const float*)d_in[6];
    float* out = (float*)d_out;

    k_zero<<<1, 256>>>();
    k_conv1<<<dim3(4, 4, 4), dim3(16, 16)>>>(x, w1, b1);
    k_hist<<<16, 256>>>(bk);
    k_scan<<<1, 256>>>();
    k_scatter<<<16, 256>>>(bk);

    size_t smem = (size_t)(64 * FSTRIDE + 64 * W2STRIDE + 144 * PSTRIDE) * sizeof(float); // 185472 B
    cudaFuncSetAttribute(k_main, cudaFuncAttributeMaxDynamicSharedMemorySize, (int)smem);
    k_main<<<NT, 256, smem>>>(x, emb, w2, b2, out);
}

// round 2
// speedup vs baseline: 1.0116x; 1.0116x over previous
#include <cuda_runtime.h>

#define HWPIX 4096
#define NT 216
#define EMBROW 36928     // 64*577
#define FTSTRIDE 68      // Ft row: 64 o's padded to 68
#define NP 32            // pixel chunk
#define PSTRIDE 34       // padded patch row
#define W2STRIDE 68
#define NSTG 5

typedef unsigned long long ull;

__device__ __forceinline__ ull pack_dup(float v) {
    ull r;
    asm("mov.b64 %0, {%1, %1};" : "=l"(r) : "f"(v));
    return r;
}
__device__ __forceinline__ void fma2(ull& acc, ull a, ull b) {
    asm("fma.rn.f32x2 %0, %1, %2, %0;" : "+l"(acc) : "l"(a), "l"(b));
}
__device__ __forceinline__ void unpack2(float& lo, float& hi, ull v) {
    asm("mov.b64 {%0, %1}, %2;" : "=f"(lo), "=f"(hi) : "l"(v));
}

// ---------- device scratch ----------
__device__ __align__(16) float g_h[HWPIX * 64];   // h in HWC layout
__device__ int g_count[NT];
__device__ int g_start[NT];
__device__ int g_order[NT];
__device__ int g_pix[HWPIX];

// ---------- fused bucketing: hist + scan + scatter + sort-by-count ----------
__global__ __launch_bounds__(256) void k_bucket(const int* __restrict__ buckets) {
    __shared__ int hist[256];
    __shared__ int cnt[256];
    __shared__ int scan[256];
    __shared__ int cur[NT];
    int tid = threadIdx.x;
    hist[tid] = 0;
    __syncthreads();
    for (int i = tid; i < HWPIX; i += 256) atomicAdd(&hist[buckets[i]], 1);
    __syncthreads();
    int v = (tid < NT) ? hist[tid] : 0;
    cnt[tid] = v;
    scan[tid] = v;
    __syncthreads();
    for (int off = 1; off < 256; off <<= 1) {
        int t = (tid >= off) ? scan[tid - off] : 0;
        __syncthreads();
        scan[tid] += t;
        __syncthreads();
    }
    int excl = scan[tid] - v;
    if (tid < NT) {
        g_count[tid] = v;
        g_start[tid] = excl;
        cur[tid] = excl;
    }
    __syncthreads();
    for (int i = tid; i < HWPIX; i += 256) {
        int b = buckets[i];
        int pos = atomicAdd(&cur[b], 1);
        g_pix[pos] = i;
    }
    // rank buckets by descending count (ties by index) -> g_order
    if (tid < NT) {
        int rank = 0;
        for (int j = 0; j < NT; j++) {
            int cj = cnt[j];
            rank += (cj > v) || (cj == v && j < tid);
        }
        g_order[rank] = tid;
    }
}

// ---------- body1: grouped 3x3 conv + bias + relu -> g_h (HWC) ----------
__global__ __launch_bounds__(256) void k_conv1(const float* __restrict__ x,
                                               const float* __restrict__ w1,
                                               const float* __restrict__ b1) {
    __shared__ float xs[16][18][18];
    __shared__ __align__(16) float wsm[144 * 20];
    int g = blockIdx.z;
    int y0 = blockIdx.y * 16, x0 = blockIdx.x * 16;
    int tid = threadIdx.y * 16 + threadIdx.x;

    for (int idx = tid; idx < 2304; idx += 256) {
        int oc = idx / 144, m = idx - oc * 144;
        wsm[m * 20 + oc] = w1[(g * 16 + oc) * 144 + m];
    }
    for (int idx = tid; idx < 16 * 324; idx += 256) {
        int ci = idx / 324, r = idx - ci * 324;
        int yl = r / 18, xl = r - yl * 18;
        int yy = y0 - 1 + yl, xx = x0 - 1 + xl;
        float v = 0.f;
        if ((unsigned)yy < 64u && (unsigned)xx < 64u)
            v = x[(g * 16 + ci) * HWPIX + yy * 64 + xx];
        xs[ci][yl][xl] = v;
    }
    __syncthreads();

    int ty = threadIdx.y, tx = threadIdx.x;
    float acc[16];
#pragma unroll
    for (int oc = 0; oc < 16; oc++) acc[oc] = __ldg(&b1[g * 16 + oc]);

    for (int ci = 0; ci < 16; ci++) {
#pragma unroll
        for (int s = 0; s < 9; s++) {
            float xv = xs[ci][ty + s / 3][tx + s % 3];
            int m = ci * 9 + s;
#pragma unroll
            for (int q = 0; q < 4; q++) {
                float4 w = *(const float4*)&wsm[m * 20 + q * 4];
                acc[q * 4 + 0] += w.x * xv;
                acc[q * 4 + 1] += w.y * xv;
                acc[q * 4 + 2] += w.z * xv;
                acc[q * 4 + 3] += w.w * xv;
            }
        }
    }
    int gy = y0 + ty, gx = x0 + tx;
    float* hp = &g_h[(gy * 64 + gx) * 64 + g * 16];
#pragma unroll
    for (int q = 0; q < 4; q++) {
        float4 r;
        r.x = fmaxf(acc[q * 4 + 0], 0.f);
        r.y = fmaxf(acc[q * 4 + 1], 0.f);
        r.z = fmaxf(acc[q * 4 + 2], 0.f);
        r.w = fmaxf(acc[q * 4 + 3], 0.f);
        *(float4*)&hp[q * 4] = r;
    }
}

// ---------- main: per-bucket dynamic conv GEMM (f32x2) + fused 1x1 + residual ----------
__global__ __launch_bounds__(256) void k_main(const float* __restrict__ x,
                                              const float* __restrict__ emb,
                                              const float* __restrict__ w2,
                                              const float* __restrict__ b2,
                                              float* __restrict__ out) {
    extern __shared__ float sm[];
    float* Ft = sm;                             // 577 x 68 (transposed filter, [ck][o])
    float* w2s = sm + 577 * FTSTRIDE;           // 64 x 68
    float* patch = w2s + 64 * W2STRIDE;         // 144 x 34 (aliased as zbuf)
    __shared__ int pixels[NP];

    int t = g_order[blockIdx.x];
    int tid = threadIdx.x;
    int n = g_count[t];
    int start = g_start[t];

    // load filter, TRANSPOSED: Ft[j*68 + o] = emb[t][o*577 + j]
    const float* e = emb + (size_t)t * EMBROW;
    for (int idx = tid * 4; idx < EMBROW; idx += 1024) {
        float4 v = *(const float4*)(e + idx);
        int o = idx / 577;
        int j = idx - o * 577;
        if (j <= 573) {
            Ft[(j + 0) * FTSTRIDE + o] = v.x;
            Ft[(j + 1) * FTSTRIDE + o] = v.y;
            Ft[(j + 2) * FTSTRIDE + o] = v.z;
            Ft[(j + 3) * FTSTRIDE + o] = v.w;
        } else {
            float vv[4] = {v.x, v.y, v.z, v.w};
#pragma unroll
            for (int q = 0; q < 4; q++) {
                int jj = j + q, oo = o;
                if (jj >= 577) { jj -= 577; oo++; }
                Ft[jj * FTSTRIDE + oo] = vv[q];
            }
        }
    }
    for (int idx = tid * 4; idx < 4096; idx += 1024) {
        *(float4*)&w2s[(idx >> 6) * W2STRIDE + (idx & 63)] = *(const float4*)(w2 + idx);
    }
    __syncthreads();

    int opq = tid >> 4;   // 0..15 : o's = opq*4 .. opq*4+3 (two f32x2 pairs)
    int pt = tid & 15;    // 0..15 : pixels {2pt, 2pt+1}

    float4 sv[NSTG];

    for (int pb = 0; pb < n; pb += NP) {
        int npc = min(NP, n - pb);
        __syncthreads();
        if (tid < NP) pixels[tid] = g_pix[start + pb + min(tid, npc - 1)];
        __syncthreads();

        // stage c0=0 into registers
#pragma unroll
        for (int i = 0; i < NSTG; i++) {
            int q = tid + i * 256;
            if (q < 1152) {
                int p = q / 36;
                int r = q - p * 36;
                int cq = r & 3, s = r >> 2;
                int pix = pixels[p];
                int yy = (pix >> 6) + s / 3 - 1, xx = (pix & 63) + s % 3 - 1;
                float4 v = make_float4(0.f, 0.f, 0.f, 0.f);
                if ((unsigned)yy < 64u && (unsigned)xx < 64u)
                    v = *(const float4*)&g_h[((yy << 6) + xx) * 64 + cq * 4];
                sv[i] = v;
            }
        }

        ull acc[2][2] = {{0ull, 0ull}, {0ull, 0ull}};  // [opair][px]

        for (int c = 0; c < 4; c++) {
            // store staged regs -> patch (patch free: guarded by sync below/above)
#pragma unroll
            for (int i = 0; i < NSTG; i++) {
                int q = tid + i * 256;
                if (q < 1152) {
                    int p = q / 36;
                    int r = q - p * 36;
                    int cq = r & 3, s = r >> 2;
                    int clb = cq * 4;
                    patch[((clb + 0) * 9 + s) * PSTRIDE + p] = sv[i].x;
                    patch[((clb + 1) * 9 + s) * PSTRIDE + p] = sv[i].y;
                    patch[((clb + 2) * 9 + s) * PSTRIDE + p] = sv[i].z;
                    patch[((clb + 3) * 9 + s) * PSTRIDE + p] = sv[i].w;
                }
            }
            __syncthreads();

            // prefetch next chunk's gmem data into regs (overlaps the FFMA block)
            if (c < 3) {
                int c0n = (c + 1) * 16;
#pragma unroll
                for (int i = 0; i < NSTG; i++) {
                    int q = tid + i * 256;
                    if (q < 1152) {
                        int p = q / 36;
                        int r = q - p * 36;
                        int cq = r & 3, s = r >> 2;
                        int pix = pixels[p];
                        int yy = (pix >> 6) + s / 3 - 1, xx = (pix & 63) + s % 3 - 1;
                        float4 v = make_float4(0.f, 0.f, 0.f, 0.f);
                        if ((unsigned)yy < 64u && (unsigned)xx < 64u)
                            v = *(const float4*)&g_h[((yy << 6) + xx) * 64 + c0n + cq * 4];
                        sv[i] = v;
                    }
                }
            }

            // GEMM on this 144-deep slab: acc += Ft[:, o] * patch[ck, p]
            {
                const float* FTb = Ft + (c * 144) * FTSTRIDE + opq * 4;
                const float* Pb = patch + pt * 2;
#pragma unroll 2
                for (int ck = 0; ck < 144; ck += 4) {
#pragma unroll
                    for (int k = 0; k < 4; k++) {
                        float4 f = *(const float4*)&FTb[(ck + k) * FTSTRIDE];
                        ull f01 = ((const ull*)&f)[0];
                        ull f23 = ((const ull*)&f)[1];
                        float2 qv = *(const float2*)&Pb[(ck + k) * PSTRIDE];
                        ull qa = pack_dup(qv.x);
                        ull qb = pack_dup(qv.y);
                        fma2(acc[0][0], f01, qa);
                        fma2(acc[1][0], f23, qa);
                        fma2(acc[0][1], f01, qb);
                        fma2(acc[1][1], f23, qb);
                    }
                }
            }
            __syncthreads();
        }

        // unpack accumulators: a[i][j], i = o offset 0..3, j = px 0..1
        float a[4][2];
        unpack2(a[0][0], a[1][0], acc[0][0]);
        unpack2(a[0][1], a[1][1], acc[0][1]);
        unpack2(a[2][0], a[3][0], acc[1][0]);
        unpack2(a[2][1], a[3][1], acc[1][1]);

        // dyn bias + relu -> zbuf (aliases patch)
        float* zbuf = patch;
#pragma unroll
        for (int i = 0; i < 4; i++) {
            int o = opq * 4 + i;
            float bsum = Ft[576 * FTSTRIDE + o];
            zbuf[o * PSTRIDE + pt * 2 + 0] = fmaxf(a[i][0] + bsum, 0.f);
            zbuf[o * PSTRIDE + pt * 2 + 1] = fmaxf(a[i][1] + bsum, 0.f);
        }
        __syncthreads();

        // 1x1 conv + b2 (f32x2 as well: pair over o via w2 rows? keep simple pairwise over px)
        float a2[4][2];
#pragma unroll
        for (int i = 0; i < 4; i++) {
            float bv = __ldg(&b2[opq * 4 + i]);
            a2[i][0] = bv;
            a2[i][1] = bv;
        }
#pragma unroll 4
        for (int o4 = 0; o4 < 64; o4 += 4) {
            float2 z0 = *(const float2*)&zbuf[(o4 + 0) * PSTRIDE + pt * 2];
            float2 z1 = *(const float2*)&zbuf[(o4 + 1) * PSTRIDE + pt * 2];
            float2 z2 = *(const float2*)&zbuf[(o4 + 2) * PSTRIDE + pt * 2];
            float2 z3 = *(const float2*)&zbuf[(o4 + 3) * PSTRIDE + pt * 2];
#pragma unroll
            for (int i = 0; i < 4; i++) {
                float4 w = *(const float4*)&w2s[(opq * 4 + i) * W2STRIDE + o4];
                a2[i][0] += w.x * z0.x; a2[i][0] += w.y * z1.x; a2[i][0] += w.z * z2.x; a2[i][0] += w.w * z3.x;
                a2[i][1] += w.x * z0.y; a2[i][1] += w.y * z1.y; a2[i][1] += w.z * z2.y; a2[i][1] += w.w * z3.y;
            }
        }

        // residual + relu + store (masked for padded lanes)
#pragma unroll
        for (int j = 0; j < 2; j++) {
            int p = pt * 2 + j;
            if (p < npc) {
                int pix = pixels[p];
#pragma unroll
                for (int i = 0; i < 4; i++) {
                    int oo = opq * 4 + i;
                    float v = a2[i][j] + __ldg(&x[oo * HWPIX + pix]);
                    out[oo * HWPIX + pix] = fmaxf(v, 0.f);
                }
            }
        }
    }
}

extern "C" void kernel_launch(void* const* d_in, const int* in_sizes, int n_in,
                              void* d_out, int out_size) {
    const float* x   = (const float*)d_in[0];
    const int* bk    = (const int*)d_in[1];
    const float* w1  = (const float*)d_in[2];
    const float* b1  = (const float*)d_in[3];
    const float* emb = (const float*)d_in[4];
    const float* w2  = (const float*)d_in[5];
    const float* b2  = (const float*)d_in[6];
    float* out = (float*)d_out;

    k_bucket<<<1, 256>>>(bk);
    k_conv1<<<dim3(4, 4, 4), dim3(16, 16)>>>(x, w1, b1);

    size_t smem = (size_t)(577 * FTSTRIDE + 64 * W2STRIDE + 144 * PSTRIDE) * sizeof(float); // 193936 B
    cudaFuncSetAttribute(k_main, cudaFuncAttributeMaxDynamicSharedMemorySize, (int)smem);
    k_main<<<NT, 256, smem>>>(x, emb, w2, b2, out);
}

// round 3
// speedup vs baseline: 1.0231x; 1.0114x over previous
#include <cuda_runtime.h>

#define HWPIX 4096
#define NT 216
#define EMBROW 36928     // 64*577
#define FTSTRIDE 68      // Ft row: 64 o's padded to 68
#define NP 32            // pixel chunk
#define PSTRIDE 34       // padded patch row
#define W2STRIDE 68
#define NSTG 5

typedef unsigned long long ull;

__device__ __forceinline__ ull pack_dup(float v) {
    ull r;
    asm("mov.b64 %0, {%1, %1};" : "=l"(r) : "f"(v));
    return r;
}
__device__ __forceinline__ void fma2(ull& acc, ull a, ull b) {
    asm("fma.rn.f32x2 %0, %1, %2, %0;" : "+l"(acc) : "l"(a), "l"(b));
}
__device__ __forceinline__ void unpack2(float& lo, float& hi, ull v) {
    asm("mov.b64 {%0, %1}, %2;" : "=f"(lo), "=f"(hi) : "l"(v));
}

// ---------- device scratch ----------
__device__ __align__(16) float g_h[HWPIX * 64];   // h in HWC layout
__device__ int g_hist4[4][NT];   // per-histblock partial histograms
__device__ int g_count[NT];
__device__ int g_start[NT];
__device__ int g_cursor[NT];
__device__ int g_order[NT];
__device__ int g_pix[HWPIX];

// ---------- launch 1: conv1 (blocks 0..63) + histogram (blocks 64..67) ----------
__global__ __launch_bounds__(256) void k_conv1hist(const float* __restrict__ x,
                                                   const float* __restrict__ w1,
                                                   const float* __restrict__ b1,
                                                   const int* __restrict__ buckets) {
    int blk = blockIdx.x;
    int tid = threadIdx.x;

    if (blk >= 64) {
        // histogram slice: 1024 pixels per block, private output slice (no pre-zero needed)
        __shared__ int hist[NT];
        int hb = blk - 64;
        for (int i = tid; i < NT; i += 256) hist[i] = 0;
        __syncthreads();
        int base = hb * 1024;
        for (int i = tid; i < 1024; i += 256) atomicAdd(&hist[buckets[base + i]], 1);
        __syncthreads();
        for (int i = tid; i < NT; i += 256) g_hist4[hb][i] = hist[i];
        return;
    }

    __shared__ float xs[16][18][18];
    __shared__ __align__(16) float wsm[144 * 20];
    int g = blk >> 4;
    int y0 = ((blk >> 2) & 3) * 16, x0 = (blk & 3) * 16;

    for (int idx = tid; idx < 2304; idx += 256) {
        int oc = idx / 144, m = idx - oc * 144;
        wsm[m * 20 + oc] = w1[(g * 16 + oc) * 144 + m];
    }
    for (int idx = tid; idx < 16 * 324; idx += 256) {
        int ci = idx / 324, r = idx - ci * 324;
        int yl = r / 18, xl = r - yl * 18;
        int yy = y0 - 1 + yl, xx = x0 - 1 + xl;
        float v = 0.f;
        if ((unsigned)yy < 64u && (unsigned)xx < 64u)
            v = x[(g * 16 + ci) * HWPIX + yy * 64 + xx];
        xs[ci][yl][xl] = v;
    }
    __syncthreads();

    int ty = tid >> 4, tx = tid & 15;
    float acc[16];
#pragma unroll
    for (int oc = 0; oc < 16; oc++) acc[oc] = __ldg(&b1[g * 16 + oc]);

    for (int ci = 0; ci < 16; ci++) {
#pragma unroll
        for (int s = 0; s < 9; s++) {
            float xv = xs[ci][ty + s / 3][tx + s % 3];
            int m = ci * 9 + s;
#pragma unroll
            for (int q = 0; q < 4; q++) {
                float4 w = *(const float4*)&wsm[m * 20 + q * 4];
                acc[q * 4 + 0] += w.x * xv;
                acc[q * 4 + 1] += w.y * xv;
                acc[q * 4 + 2] += w.z * xv;
                acc[q * 4 + 3] += w.w * xv;
            }
        }
    }
    int gy = y0 + ty, gx = x0 + tx;
    float* hp = &g_h[(gy * 64 + gx) * 64 + g * 16];
#pragma unroll
    for (int q = 0; q < 4; q++) {
        float4 r;
        r.x = fmaxf(acc[q * 4 + 0], 0.f);
        r.y = fmaxf(acc[q * 4 + 1], 0.f);
        r.z = fmaxf(acc[q * 4 + 2], 0.f);
        r.w = fmaxf(acc[q * 4 + 3], 0.f);
        *(float4*)&hp[q * 4] = r;
    }
}

// ---------- launch 2: sum partials + scan + rank (1 block) ----------
__global__ __launch_bounds__(256) void k_scan() {
    __shared__ int cnt[256];
    __shared__ int scan[256];
    int tid = threadIdx.x;
    int v = 0;
    if (tid < NT) v = g_hist4[0][tid] + g_hist4[1][tid] + g_hist4[2][tid] + g_hist4[3][tid];
    cnt[tid] = v;
    scan[tid] = v;
    __syncthreads();
    for (int off = 1; off < 256; off <<= 1) {
        int t = (tid >= off) ? scan[tid - off] : 0;
        __syncthreads();
        scan[tid] += t;
        __syncthreads();
    }
    if (tid < NT) {
        int excl = scan[tid] - v;
        g_count[tid] = v;
        g_start[tid] = excl;
        g_cursor[tid] = excl;
        // rank buckets by descending count -> big buckets first
        int rank = 0;
        for (int j = 0; j < NT; j++) {
            int cj = cnt[j];
            rank += (cj > v) || (cj == v && j < tid);
        }
        g_order[rank] = tid;
    }
}

// ---------- launch 3: scatter pixel indices ----------
__global__ __launch_bounds__(256) void k_scatter(const int* __restrict__ buckets) {
    int i = blockIdx.x * 256 + threadIdx.x;
    int b = buckets[i];
    int pos = atomicAdd(&g_cursor[b], 1);
    g_pix[pos] = i;
}

// ---------- launch 4 (ncu profiles this one): per-bucket dynamic conv GEMM ----------
__global__ __launch_bounds__(256) void k_main(const float* __restrict__ x,
                                              const float* __restrict__ emb,
                                              const float* __restrict__ w2,
                                              const float* __restrict__ b2,
                                              float* __restrict__ out) {
    extern __shared__ float sm[];
    float* Ft = sm;                             // 577 x 68 (transposed filter, [ck][o])
    float* w2s = sm + 577 * FTSTRIDE;           // 64 x 68
    float* patch = w2s + 64 * W2STRIDE;         // 144 x 34 (aliased as zbuf)
    __shared__ int pixels[NP];

    int t = g_order[blockIdx.x];
    int tid = threadIdx.x;
    int n = g_count[t];
    int start = g_start[t];

    // load filter, TRANSPOSED: Ft[j*68 + o] = emb[t][o*577 + j]
    const float* e = emb + (size_t)t * EMBROW;
    for (int idx = tid * 4; idx < EMBROW; idx += 1024) {
        float4 v = *(const float4*)(e + idx);
        int o = idx / 577;
        int j = idx - o * 577;
        if (j <= 573) {
            Ft[(j + 0) * FTSTRIDE + o] = v.x;
            Ft[(j + 1) * FTSTRIDE + o] = v.y;
            Ft[(j + 2) * FTSTRIDE + o] = v.z;
            Ft[(j + 3) * FTSTRIDE + o] = v.w;
        } else {
            float vv[4] = {v.x, v.y, v.z, v.w};
#pragma unroll
            for (int q = 0; q < 4; q++) {
                int jj = j + q, oo = o;
                if (jj >= 577) { jj -= 577; oo++; }
                Ft[jj * FTSTRIDE + oo] = vv[q];
            }
        }
    }
    for (int idx = tid * 4; idx < 4096; idx += 1024) {
        *(float4*)&w2s[(idx >> 6) * W2STRIDE + (idx & 63)] = *(const float4*)(w2 + idx);
    }
    __syncthreads();

    int opq = tid >> 4;   // 0..15 : o's = opq*4 .. opq*4+3
    int pt = tid & 15;    // 0..15 : pixels {2pt, 2pt+1}

    // ---- precompute per-thread staging decomposition (loop-invariant) ----
    int pp[NSTG], soff[NSTG], sy[NSTG], sx[NSTG];
    bool qv_ok[NSTG];
#pragma unroll
    for (int i = 0; i < NSTG; i++) {
        int q = tid + i * 256;
        qv_ok[i] = (q < 1152);
        int qq = qv_ok[i] ? q : 0;
        int p = qq / 36;
        int r = qq - p * 36;
        int cq = r & 3, s = r >> 2;
        pp[i] = p;
        sy[i] = s / 3 - 1;
        sx[i] = s % 3 - 1;
        soff[i] = ((cq * 4) * 9 + s) * PSTRIDE + p;   // patch store offset for channel lane 0
    }
    int chq[NSTG];
#pragma unroll
    for (int i = 0; i < NSTG; i++) {
        int q = tid + i * 256;
        int r = qv_ok[i] ? (q - (q / 36) * 36) : 0;
        chq[i] = (r & 3) * 4;                         // channel sub-offset within slab
    }

    float4 sv[NSTG];

    for (int pb = 0; pb < n; pb += NP) {
        int npc = min(NP, n - pb);
        __syncthreads();
        if (tid < NP) pixels[tid] = g_pix[start + pb + min(tid, npc - 1)];
        __syncthreads();

        // stage slab c=0 into registers
#pragma unroll
        for (int i = 0; i < NSTG; i++) {
            if (qv_ok[i]) {
                int pix = pixels[pp[i]];
                int yy = (pix >> 6) + sy[i], xx = (pix & 63) + sx[i];
                float4 v = make_float4(0.f, 0.f, 0.f, 0.f);
                if ((unsigned)yy < 64u && (unsigned)xx < 64u)
                    v = *(const float4*)&g_h[((yy << 6) + xx) * 64 + chq[i]];
                sv[i] = v;
            }
        }

        ull acc[2][2] = {{0ull, 0ull}, {0ull, 0ull}};  // [opair][px]

        for (int c = 0; c < 4; c++) {
            // store staged regs -> patch
#pragma unroll
            for (int i = 0; i < NSTG; i++) {
                if (qv_ok[i]) {
                    patch[soff[i] + 0 * 9 * PSTRIDE] = sv[i].x;
                    patch[soff[i] + 1 * 9 * PSTRIDE] = sv[i].y;
                    patch[soff[i] + 2 * 9 * PSTRIDE] = sv[i].z;
                    patch[soff[i] + 3 * 9 * PSTRIDE] = sv[i].w;
                }
            }
            __syncthreads();

            // prefetch next slab (overlaps the FFMA block)
            if (c < 3) {
                int c0n = (c + 1) * 16;
#pragma unroll
                for (int i = 0; i < NSTG; i++) {
                    if (qv_ok[i]) {
                        int pix = pixels[pp[i]];
                        int yy = (pix >> 6) + sy[i], xx = (pix & 63) + sx[i];
                        float4 v = make_float4(0.f, 0.f, 0.f, 0.f);
                        if ((unsigned)yy < 64u && (unsigned)xx < 64u)
                            v = *(const float4*)&g_h[((yy << 6) + xx) * 64 + c0n + chq[i]];
                        sv[i] = v;
                    }
                }
            }

            // GEMM on this 144-deep slab
            {
                const float* FTb = Ft + (c * 144) * FTSTRIDE + opq * 4;
                const float* Pb = patch + pt * 2;
#pragma unroll 2
                for (int ck = 0; ck < 144; ck += 4) {
#pragma unroll
                    for (int k = 0; k < 4; k++) {
                        float4 f = *(const float4*)&FTb[(ck + k) * FTSTRIDE];
                        ull f01 = ((const ull*)&f)[0];
                        ull f23 = ((const ull*)&f)[1];
                        float2 qv = *(const float2*)&Pb[(ck + k) * PSTRIDE];
                        ull qa = pack_dup(qv.x);
                        ull qb = pack_dup(qv.y);
                        fma2(acc[0][0], f01, qa);
                        fma2(acc[1][0], f23, qa);
                        fma2(acc[0][1], f01, qb);
                        fma2(acc[1][1], f23, qb);
                    }
                }
            }
            __syncthreads();
        }

        float a[4][2];
        unpack2(a[0][0], a[1][0], acc[0][0]);
        unpack2(a[0][1], a[1][1], acc[0][1]);
        unpack2(a[2][0], a[3][0], acc[1][0]);
        unpack2(a[2][1], a[3][1], acc[1][1]);

        // dyn bias + relu -> zbuf (aliases patch)
        float* zbuf = patch;
#pragma unroll
        for (int i = 0; i < 4; i++) {
            int o = opq * 4 + i;
            float bsum = Ft[576 * FTSTRIDE + o];
            zbuf[o * PSTRIDE + pt * 2 + 0] = fmaxf(a[i][0] + bsum, 0.f);
            zbuf[o * PSTRIDE + pt * 2 + 1] = fmaxf(a[i][1] + bsum, 0.f);
        }
        __syncthreads();

        // 1x1 conv + b2
        float a2[4][2];
#pragma unroll
        for (int i = 0; i < 4; i++) {
            float bv = __ldg(&b2[opq * 4 + i]);
            a2[i][0] = bv;
            a2[i][1] = bv;
        }
#pragma unroll 4
        for (int o4 = 0; o4 < 64; o4 += 4) {
            float2 z0 = *(const float2*)&zbuf[(o4 + 0) * PSTRIDE + pt * 2];
            float2 z1 = *(const float2*)&zbuf[(o4 + 1) * PSTRIDE + pt * 2];
            float2 z2 = *(const float2*)&zbuf[(o4 + 2) * PSTRIDE + pt * 2];
            float2 z3 = *(const float2*)&zbuf[(o4 + 3) * PSTRIDE + pt * 2];
#pragma unroll
            for (int i = 0; i < 4; i++) {
                float4 w = *(const float4*)&w2s[(opq * 4 + i) * W2STRIDE + o4];
                a2[i][0] += w.x * z0.x; a2[i][0] += w.y * z1.x; a2[i][0] += w.z * z2.x; a2[i][0] += w.w * z3.x;
                a2[i][1] += w.x * z0.y; a2[i][1] += w.y * z1.y; a2[i][1] += w.z * z2.y; a2[i][1] += w.w * z3.y;
            }
        }

        // residual + relu + store
#pragma unroll
        for (int j = 0; j < 2; j++) {
            int p = pt * 2 + j;
            if (p < npc) {
                int pix = pixels[p];
#pragma unroll
                for (int i = 0; i < 4; i++) {
                    int oo = opq * 4 + i;
                    float v = a2[i][j] + __ldg(&x[oo * HWPIX + pix]);
                    out[oo * HWPIX + pix] = fmaxf(v, 0.f);
                }
            }
        }
    }
}

extern "C" void kernel_launch(void* const* d_in, const int* in_sizes, int n_in,
                              void* d_out, int out_size) {
    const float* x   = (const float*)d_in[0];
    const int* bk    = (const int*)d_in[1];
    const float* w1  = (const float*)d_in[2];
    const float* b1  = (const float*)d_in[3];
    const float* emb = (const float*)d_in[4];
    const float* w2  = (const float*)d_in[5];
    const float* b2  = (const float*)d_in[6];
    float* out = (float*)d_out;

    k_conv1hist<<<68, 256>>>(x, w1, b1, bk);
    k_scan<<<1, 256>>>();
    k_scatter<<<16, 256>>>(bk);

    size_t smem = (size_t)(577 * FTSTRIDE + 64 * W2STRIDE + 144 * PSTRIDE) * sizeof(float); // 193936 B
    cudaFuncSetAttribute(k_main, cudaFuncAttributeMaxDynamicSharedMemorySize, (int)smem);
    k_main<<<NT, 256, smem>>>(x, emb, w2, b2, out);
}

// round 4
// speedup vs baseline: 1.1314x; 1.1058x over previous
#include <cuda_runtime.h>

#define HWPIX 4096
#define NT 216
#define EMBROW 36928     // 64*577 floats
#define EMBBYTES 147712  // EMBROW*4
#define FROW 577         // dense F row stride (floats)
#define NP 32            // pixel chunk
#define PSTRIDE 34       // padded patch row
#define W2STRIDE 68
#define NSTG 5

typedef unsigned long long ull;

__device__ __forceinline__ ull pack_dup(float v) {
    ull r;
    asm("mov.b64 %0, {%1, %1};" : "=l"(r) : "f"(v));
    return r;
}
__device__ __forceinline__ void fma2(ull& acc, ull a, ull b) {
    asm("fma.rn.f32x2 %0, %1, %2, %0;" : "+l"(acc) : "l"(a), "l"(b));
}
__device__ __forceinline__ void unpack2(float& lo, float& hi, ull v) {
    asm("mov.b64 {%0, %1}, %2;" : "=f"(lo), "=f"(hi) : "l"(v));
}
__device__ __forceinline__ unsigned smem_u32(const void* p) {
    unsigned a;
    asm("{ .reg .u64 t; cvta.to.shared.u64 t, %1; cvt.u32.u64 %0, t; }" : "=r"(a) : "l"(p));
    return a;
}

// ---------- device scratch ----------
__device__ __align__(16) float g_h[HWPIX * 64];   // h in HWC layout
__device__ int g_hist4[4][NT];
__device__ int g_count[NT];
__device__ int g_start[NT];
__device__ int g_cursor[NT];
__device__ int g_order[NT];
__device__ int g_pix[HWPIX];

// ---------- launch 1: conv1 (blocks 0..63) + histogram (blocks 64..67) ----------
__global__ __launch_bounds__(256) void k_conv1hist(const float* __restrict__ x,
                                                   const float* __restrict__ w1,
                                                   const float* __restrict__ b1,
                                                   const int* __restrict__ buckets) {
    int blk = blockIdx.x;
    int tid = threadIdx.x;

    if (blk >= 64) {
        __shared__ int hist[NT];
        int hb = blk - 64;
        for (int i = tid; i < NT; i += 256) hist[i] = 0;
        __syncthreads();
        int base = hb * 1024;
        for (int i = tid; i < 1024; i += 256) atomicAdd(&hist[buckets[base + i]], 1);
        __syncthreads();
        for (int i = tid; i < NT; i += 256) g_hist4[hb][i] = hist[i];
        return;
    }

    __shared__ float xs[16][18][18];
    __shared__ __align__(16) float wsm[144 * 20];
    int g = blk >> 4;
    int y0 = ((blk >> 2) & 3) * 16, x0 = (blk & 3) * 16;

    for (int idx = tid; idx < 2304; idx += 256) {
        int oc = idx / 144, m = idx - oc * 144;
        wsm[m * 20 + oc] = w1[(g * 16 + oc) * 144 + m];
    }
    for (int idx = tid; idx < 16 * 324; idx += 256) {
        int ci = idx / 324, r = idx - ci * 324;
        int yl = r / 18, xl = r - yl * 18;
        int yy = y0 - 1 + yl, xx = x0 - 1 + xl;
        float v = 0.f;
        if ((unsigned)yy < 64u && (unsigned)xx < 64u)
            v = x[(g * 16 + ci) * HWPIX + yy * 64 + xx];
        xs[ci][yl][xl] = v;
    }
    __syncthreads();

    int ty = tid >> 4, tx = tid & 15;
    float acc[16];
#pragma unroll
    for (int oc = 0; oc < 16; oc++) acc[oc] = __ldg(&b1[g * 16 + oc]);

    for (int ci = 0; ci < 16; ci++) {
#pragma unroll
        for (int s = 0; s < 9; s++) {
            float xv = xs[ci][ty + s / 3][tx + s % 3];
            int m = ci * 9 + s;
#pragma unroll
            for (int q = 0; q < 4; q++) {
                float4 w = *(const float4*)&wsm[m * 20 + q * 4];
                acc[q * 4 + 0] += w.x * xv;
                acc[q * 4 + 1] += w.y * xv;
                acc[q * 4 + 2] += w.z * xv;
                acc[q * 4 + 3] += w.w * xv;
            }
        }
    }
    int gy = y0 + ty, gx = x0 + tx;
    float* hp = &g_h[(gy * 64 + gx) * 64 + g * 16];
#pragma unroll
    for (int q = 0; q < 4; q++) {
        float4 r;
        r.x = fmaxf(acc[q * 4 + 0], 0.f);
        r.y = fmaxf(acc[q * 4 + 1], 0.f);
        r.z = fmaxf(acc[q * 4 + 2], 0.f);
        r.w = fmaxf(acc[q * 4 + 3], 0.f);
        *(float4*)&hp[q * 4] = r;
    }
}

// ---------- launch 2: sum partials + scan + rank ----------
__global__ __launch_bounds__(256) void k_scan() {
    __shared__ int cnt[256];
    __shared__ int scan[256];
    int tid = threadIdx.x;
    int v = 0;
    if (tid < NT) v = g_hist4[0][tid] + g_hist4[1][tid] + g_hist4[2][tid] + g_hist4[3][tid];
    cnt[tid] = v;
    scan[tid] = v;
    __syncthreads();
    for (int off = 1; off < 256; off <<= 1) {
        int t = (tid >= off) ? scan[tid - off] : 0;
        __syncthreads();
        scan[tid] += t;
        __syncthreads();
    }
    if (tid < NT) {
        int excl = scan[tid] - v;
        g_count[tid] = v;
        g_start[tid] = excl;
        g_cursor[tid] = excl;
        int rank = 0;
        for (int j = 0; j < NT; j++) {
            int cj = cnt[j];
            rank += (cj > v) || (cj == v && j < tid);
        }
        g_order[rank] = tid;
    }
}

// ---------- launch 3: scatter ----------
__global__ __launch_bounds__(256) void k_scatter(const int* __restrict__ buckets) {
    int i = blockIdx.x * 256 + threadIdx.x;
    int b = buckets[i];
    int pos = atomicAdd(&g_cursor[b], 1);
    g_pix[pos] = i;
}

// ---------- launch 4: per-bucket dynamic conv GEMM, F via TMA bulk ----------
__global__ __launch_bounds__(256) void k_main(const float* __restrict__ x,
                                              const float* __restrict__ emb,
                                              const float* __restrict__ w2,
                                              const float* __restrict__ b2,
                                              float* __restrict__ out) {
    extern __shared__ float sm[];
    float* Fs = sm;                             // 64 x 577 dense (TMA target)
    float* w2s = sm + EMBROW;                   // 64 x 68
    float* patch = w2s + 64 * W2STRIDE;         // 144 x 34 (aliased as zbuf)
    __shared__ int pixels[NP];
    __shared__ __align__(8) ull mbar;

    int t = g_order[blockIdx.x];
    int tid = threadIdx.x;
    int n = g_count[t];
    int start = g_start[t];

    // --- issue async bulk copy of this bucket's filter (147712 B) ---
    unsigned mb = smem_u32(&mbar);
    if (tid == 0) {
        asm volatile("mbarrier.init.shared.b64 [%0], 1;" :: "r"(mb) : "memory");
        asm volatile("fence.proxy.async.shared::cta;" ::: "memory");
        asm volatile("mbarrier.arrive.expect_tx.shared.b64 _, [%0], %1;"
                     :: "r"(mb), "r"(EMBBYTES) : "memory");
        asm volatile("cp.async.bulk.shared::cta.global.mbarrier::complete_tx::bytes "
                     "[%0], [%1], %2, [%3];"
                     :: "r"(smem_u32(Fs)), "l"(emb + (size_t)t * EMBROW),
                        "r"(EMBBYTES), "r"(mb) : "memory");
    }

    // w2 (16KB, L2-hot) via regular loads, padded rows
    for (int idx = tid * 4; idx < 4096; idx += 1024) {
        *(float4*)&w2s[(idx >> 6) * W2STRIDE + (idx & 63)] = *(const float4*)(w2 + idx);
    }

    int opq = tid >> 3;   // 0..31 : o's = opq*2, opq*2+1
    int pt = tid & 7;     // 0..7  : pixels 4pt .. 4pt+3

    // precomputed staging decomposition (loop-invariant)
    int pp[NSTG], soff[NSTG], sy[NSTG], sx[NSTG], chq[NSTG];
    bool qv_ok[NSTG];
#pragma unroll
    for (int i = 0; i < NSTG; i++) {
        int q = tid + i * 256;
        qv_ok[i] = (q < 1152);
        int qq = qv_ok[i] ? q : 0;
        int p = qq / 36;
        int r = qq - p * 36;
        int cq = r & 3, s = r >> 2;
        pp[i] = p;
        sy[i] = s / 3 - 1;
        sx[i] = s % 3 - 1;
        soff[i] = ((cq * 4) * 9 + s) * PSTRIDE + p;
        chq[i] = cq * 4;
    }

    float4 sv[NSTG];
    bool waited = false;

    for (int pb = 0; pb < n; pb += NP) {
        int npc = min(NP, n - pb);
        __syncthreads();
        if (tid < NP) pixels[tid] = g_pix[start + pb + min(tid, npc - 1)];
        __syncthreads();

        // stage slab c=0
#pragma unroll
        for (int i = 0; i < NSTG; i++) {
            if (qv_ok[i]) {
                int pix = pixels[pp[i]];
                int yy = (pix >> 6) + sy[i], xx = (pix & 63) + sx[i];
                float4 v = make_float4(0.f, 0.f, 0.f, 0.f);
                if ((unsigned)yy < 64u && (unsigned)xx < 64u)
                    v = *(const float4*)&g_h[((yy << 6) + xx) * 64 + chq[i]];
                sv[i] = v;
            }
        }

        ull acc00 = 0, acc01 = 0, acc10 = 0, acc11 = 0;  // [o-lane][px-pair]

        for (int c = 0; c < 4; c++) {
#pragma unroll
            for (int i = 0; i < NSTG; i++) {
                if (qv_ok[i]) {
                    patch[soff[i] + 0 * 9 * PSTRIDE] = sv[i].x;
                    patch[soff[i] + 1 * 9 * PSTRIDE] = sv[i].y;
                    patch[soff[i] + 2 * 9 * PSTRIDE] = sv[i].z;
                    patch[soff[i] + 3 * 9 * PSTRIDE] = sv[i].w;
                }
            }
            __syncthreads();

            if (c < 3) {
                int c0n = (c + 1) * 16;
#pragma unroll
                for (int i = 0; i < NSTG; i++) {
                    if (qv_ok[i]) {
                        int pix = pixels[pp[i]];
                        int yy = (pix >> 6) + sy[i], xx = (pix & 63) + sx[i];
                        float4 v = make_float4(0.f, 0.f, 0.f, 0.f);
                        if ((unsigned)yy < 64u && (unsigned)xx < 64u)
                            v = *(const float4*)&g_h[((yy << 6) + xx) * 64 + c0n + chq[i]];
                        sv[i] = v;
                    }
                }
            }

            // F must be resident before first GEMM
            if (!waited) {
                unsigned done;
                do {
                    asm volatile("{\n\t.reg .pred p;\n\t"
                                 "mbarrier.try_wait.parity.acquire.cta.shared::cta.b64 p, [%1], 0, 0x989680;\n\t"
                                 "selp.b32 %0, 1, 0, p;\n\t}"
                                 : "=r"(done) : "r"(mb) : "memory");
                } while (!done);
                waited = true;
            }

            // GEMM slab: acc[o][ppair] += F[o][j] * patch[ck][px]
            {
                const float* F0 = Fs + (opq * 2) * FROW + c * 144;
                const float* F1 = F0 + FROW;
                const float* Pb = patch + pt * 4;
#pragma unroll 4
                for (int ck = 0; ck < 144; ck++) {
                    ull da = pack_dup(F0[ck]);
                    ull db = pack_dup(F1[ck]);
                    ull p01 = *(const ull*)&Pb[ck * PSTRIDE];
                    ull p23 = *(const ull*)&Pb[ck * PSTRIDE + 2];
                    fma2(acc00, da, p01);
                    fma2(acc01, da, p23);
                    fma2(acc10, db, p01);
                    fma2(acc11, db, p23);
                }
            }
            __syncthreads();
        }

        // unpack: a[o-lane][px]
        float a[2][4];
        unpack2(a[0][0], a[0][1], acc00);
        unpack2(a[0][2], a[0][3], acc01);
        unpack2(a[1][0], a[1][1], acc10);
        unpack2(a[1][2], a[1][3], acc11);

        // dyn bias + relu -> zbuf (aliases patch, rows stride PSTRIDE)
        float* zbuf = patch;
#pragma unroll
        for (int i = 0; i < 2; i++) {
            int o = opq * 2 + i;
            float bs = Fs[o * FROW + 576];
#pragma unroll
            for (int j = 0; j < 4; j++)
                zbuf[o * PSTRIDE + pt * 4 + j] = fmaxf(a[i][j] + bs, 0.f);
        }
        __syncthreads();

        // 1x1 conv + b2 (f32x2 over px pairs, w2 scalar dup)
        ull b00, b01, b10, b11;
        {
            float bv0 = __ldg(&b2[opq * 2]);
            float bv1 = __ldg(&b2[opq * 2 + 1]);
            b00 = pack_dup(bv0); b01 = b00;
            b10 = pack_dup(bv1); b11 = b10;
        }
        {
            const float* zb = zbuf + pt * 4;
            const float* wr0 = w2s + (opq * 2) * W2STRIDE;
            const float* wr1 = wr0 + W2STRIDE;
#pragma unroll 4
            for (int z = 0; z < 64; z++) {
                ull wa = pack_dup(wr0[z]);
                ull wb = pack_dup(wr1[z]);
                ull z01 = *(const ull*)&zb[z * PSTRIDE];
                ull z23 = *(const ull*)&zb[z * PSTRIDE + 2];
                fma2(b00, wa, z01);
                fma2(b01, wa, z23);
                fma2(b10, wb, z01);
                fma2(b11, wb, z23);
            }
        }
        float a2[2][4];
        unpack2(a2[0][0], a2[0][1], b00);
        unpack2(a2[0][2], a2[0][3], b01);
        unpack2(a2[1][0], a2[1][1], b10);
        unpack2(a2[1][2], a2[1][3], b11);

        // residual + relu + store
#pragma unroll
        for (int j = 0; j < 4; j++) {
            int p = pt * 4 + j;
            if (p < npc) {
                int pix = pixels[p];
#pragma unroll
                for (int i = 0; i < 2; i++) {
                    int oo = opq * 2 + i;
                    float v = a2[i][j] + __ldg(&x[oo * HWPIX + pix]);
                    out[oo * HWPIX + pix] = fmaxf(v, 0.f);
                }
            }
        }
    }
}

extern "C" void kernel_launch(void* const* d_in, const int* in_sizes, int n_in,
                              void* d_out, int out_size) {
    const float* x   = (const float*)d_in[0];
    const int* bk    = (const int*)d_in[1];
    const float* w1  = (const float*)d_in[2];
    const float* b1  = (const float*)d_in[3];
    const float* emb = (const float*)d_in[4];
    const float* w2  = (const float*)d_in[5];
    const float* b2  = (const float*)d_in[6];
    float* out = (float*)d_out;

    k_conv1hist<<<68, 256>>>(x, w1, b1, bk);
    k_scan<<<1, 256>>>();
    k_scatter<<<16, 256>>>(bk);

    size_t smem = (size_t)(EMBROW + 64 * W2STRIDE + 144 * PSTRIDE) * sizeof(float); // 184704 B
    cudaFuncSetAttribute(k_main, cudaFuncAttributeMaxDynamicSharedMemorySize, (int)smem);
    k_main<<<NT, 256, smem>>>(x, emb, w2, b2, out);
}